// round 9
// baseline (speedup 1.0000x reference)
#include <cuda_runtime.h>
#include <math.h>

// Problem constants (setup_inputs is deterministic: B=512, K=4)
#define BATCH 512
#define TOPK 4
#define NCAPS 181
#define ICAPS 96
#define CDIM 16
#define A2 128           // 2 * num_antennas
#define MLPM (BATCH*TOPK) // 2048

// ---------------- scratch (device globals; no runtime allocation) -----------
__device__ float g_h1[BATCH*64*49];          // conv1 out
__device__ float g_h2[BATCH*128*36];         // conv2 out
__device__ float g_h3[BATCH*256*25];         // conv3 out
__device__ float g_u [BATCH*ICAPS*CDIM];     // squashed primary caps
__device__ float g_uhat[(size_t)BATCH*NCAPS*ICAPS*CDIM]; // 569 MB fp32
__device__ float g_c1[NCAPS*ICAPS];          // iter-1 coupling (batch-independent)
__device__ float g_blog[BATCH*NCAPS*ICAPS];  // routing logits
__device__ float g_maxl[BATCH*ICAPS];
__device__ float g_sume[BATCH*ICAPS];
__device__ float g_x  [BATCH*NCAPS*CDIM];    // final v
__device__ float g_len[BATCH*NCAPS];         // unnormalized lengths
__device__ int   g_idx[BATCH*TOPK];
__device__ float g_f1[MLPM*1024];
__device__ float g_f2[MLPM*768];
__device__ float g_f3[MLPM*512];
__device__ float g_f4[MLPM*512];
__device__ float g_f5[MLPM*256];

__device__ __forceinline__ float gelu_exact(float v) {
    return 0.5f * v * (1.0f + erff(v * 0.70710678118654752440f));
}

// ---------------- conv stack -------------------------------------------------
__global__ void conv1_kernel(const float* __restrict__ x, const float* __restrict__ w,
                             const float* __restrict__ bias) {
    int b = blockIdx.x, t = threadIdx.x;
    __shared__ float ins[192];   // 3x8x8
    __shared__ float ws[768];    // 64x3x2x2
    if (t < 192) ins[t] = x[b*192 + t];
    for (int j = t; j < 768; j += 256) ws[j] = w[j];
    __syncthreads();
    for (int p = t; p < 64*49; p += 256) {
        int oc = p / 49, pos = p % 49, y = pos / 7, xx = pos % 7;
        float acc = bias[oc];
        #pragma unroll
        for (int ic = 0; ic < 3; ic++)
            #pragma unroll
            for (int ky = 0; ky < 2; ky++)
                #pragma unroll
                for (int kx = 0; kx < 2; kx++)
                    acc += ws[((oc*3+ic)*2+ky)*2+kx] * ins[ic*64 + (y+ky)*8 + xx+kx];
        g_h1[b*3136 + p] = gelu_exact(acc);
    }
}

// conv2: [B,64,7,7] -> [B,128,6,6]. One out-channel per thread, 2 images/block.
__global__ void conv2_kernel(const float* __restrict__ w, const float* __restrict__ bias) {
    int b0 = blockIdx.x * 2, t = threadIdx.x;       // 256 threads
    int img = t >> 7, oc = t & 127;
    __shared__ float ins[2][64*49];                 // 25.1 KB
    for (int j = t; j < 2*64*49; j += 256) ins[j/3136][j%3136] = g_h1[b0*3136 + j];
    __syncthreads();
    const float* inp = ins[img];
    float acc[36];
    {
        float bv = bias[oc];
        #pragma unroll
        for (int p = 0; p < 36; p++) acc[p] = bv;
    }
    const float4* wp4 = (const float4*)(w + oc*256);
    for (int ic = 0; ic < 64; ic++) {
        float4 wv = wp4[ic];
        const float* r = &inp[ic*49];
        #pragma unroll
        for (int y = 0; y < 6; y++)
            #pragma unroll
            for (int xx = 0; xx < 6; xx++)
                acc[y*6+xx] += wv.x*r[y*7+xx] + wv.y*r[y*7+xx+1]
                             + wv.z*r[y*7+xx+7] + wv.w*r[y*7+xx+8];
    }
    float* outp = &g_h2[(b0+img)*4608 + oc*36];
    #pragma unroll
    for (int p = 0; p < 36; p++) outp[p] = gelu_exact(acc[p]);
}

// conv3: [B,128,6,6] -> [B,256,5,5]. One out-channel per thread, 1 image/block.
__global__ void conv3_kernel(const float* __restrict__ w, const float* __restrict__ bias) {
    int b = blockIdx.x, oc = threadIdx.x;           // 256 threads
    __shared__ float ins[128*36];                   // 18 KB
    for (int j = oc; j < 128*36; j += 256) ins[j] = g_h2[b*4608 + j];
    __syncthreads();
    float acc[25];
    {
        float bv = bias[oc];
        #pragma unroll
        for (int p = 0; p < 25; p++) acc[p] = bv;
    }
    const float4* wp4 = (const float4*)(w + oc*512);
    for (int ic = 0; ic < 128; ic++) {
        float4 wv = wp4[ic];
        const float* r = &ins[ic*36];
        #pragma unroll
        for (int y = 0; y < 5; y++)
            #pragma unroll
            for (int xx = 0; xx < 5; xx++)
                acc[y*5+xx] += wv.x*r[y*6+xx] + wv.y*r[y*6+xx+1]
                             + wv.z*r[y*6+xx+6] + wv.w*r[y*6+xx+7];
    }
    float* outp = &g_h3[b*6400 + oc*25];
    #pragma unroll
    for (int p = 0; p < 25; p++) outp[p] = gelu_exact(acc[p]);
}

// primary caps: [B,256,5,5] -> [B,96,16] + squash.
// 192 threads: (oc, half) per thread, 8 outputs each; squash via smem.
__global__ void pc_kernel(const float* __restrict__ w, const float* __restrict__ bias) {
    int b = blockIdx.x, t = threadIdx.x;            // 192 threads
    int half = t / 96, oc = t - half*96;
    __shared__ float ins[256*25];                   // 25.6 KB
    __shared__ float outs[96*16];
    for (int j = t; j < 256*25; j += 192) ins[j] = g_h3[b*6400 + j];
    __syncthreads();
    float acc[8];
    {
        float bv = bias[oc];
        #pragma unroll
        for (int p = 0; p < 8; p++) acc[p] = bv;
    }
    const float4* wp4 = (const float4*)(w + oc*1024);
    int ybase = half*2;
    for (int ic = 0; ic < 256; ic++) {
        float4 wv = wp4[ic];
        const float* r = &ins[ic*25 + ybase*5];
        #pragma unroll
        for (int yy = 0; yy < 2; yy++)
            #pragma unroll
            for (int xx = 0; xx < 4; xx++)
                acc[yy*4+xx] += wv.x*r[yy*5+xx] + wv.y*r[yy*5+xx+1]
                              + wv.z*r[yy*5+xx+5] + wv.w*r[yy*5+xx+6];
    }
    #pragma unroll
    for (int p = 0; p < 8; p++) outs[oc*16 + half*8 + p] = acc[p];
    __syncthreads();
    if (t < 96) {
        float n2 = 0.f;
        float v[16];
        #pragma unroll
        for (int d = 0; d < 16; d++) { v[d] = outs[t*16 + d]; n2 += v[d]*v[d]; }
        float n = sqrtf(n2);
        float sc = (1.0f - expf(-n)) / (n + 1e-8f);
        float* outp = &g_u[(b*96 + t)*16];
        #pragma unroll
        for (int d = 0; d < 16; d++) outp[d] = v[d] * sc;
    }
}

// ---------------- capsule layer ---------------------------------------------
// c1[o,i] = softmax over o of caps_b (batch-independent; caps_b broadcast over batch)
__global__ void c1_kernel(const float* __restrict__ caps_b) {
    int i = threadIdx.x;   // 96 threads, 1 block
    float m = -INFINITY;
    for (int o = 0; o < NCAPS; o++) m = fmaxf(m, caps_b[o*ICAPS + i]);
    float s = 0.f;
    for (int o = 0; o < NCAPS; o++) s += expf(caps_b[o*ICAPS + i] - m);
    for (int o = 0; o < NCAPS; o++)
        g_c1[o*ICAPS + i] = expf(caps_b[o*ICAPS + i] - m) / s;
}

// Fused einsum + routing iteration 1.
// Grid (NCAPS, 4), 384 threads. Thread (i = t>>2, dq = t&3) holds W[o,i,dq*4..+3,:]
// in registers; per b: compute u_hat (write fp32), s1 = sum_i c1*u_hat, squash -> v1,
// b-update dot, write post-iter1 logits to g_blog.
#define EBT 128
__global__ __launch_bounds__(384) void einsum_iter1_kernel(
        const float* __restrict__ W, const float* __restrict__ caps_b) {
    int o = blockIdx.x, bt = blockIdx.y;
    int t = threadIdx.x;
    int i = t >> 2, dq = t & 3;
    int lane = t & 31, warp = t >> 5;
    __shared__ float4 usm[384];        // u[b] : 96x16 floats
    __shared__ float c1sm[96], cbsm[96];
    __shared__ float4 s1p[12][4];      // per-warp partial s1
    __shared__ float4 vsm[4];          // v1 (16 floats)
    if (t < 96) { c1sm[t] = g_c1[o*ICAPS + t]; cbsm[t] = caps_b[o*ICAPS + t]; }
    // W[o,i, dq*4+d4, kq*4..] into registers
    float4 wv[4][4];
    const float4* wp = (const float4*)(W + ((size_t)(o*ICAPS + i)*CDIM + dq*4)*CDIM);
    #pragma unroll
    for (int d4 = 0; d4 < 4; d4++)
        #pragma unroll
        for (int kq = 0; kq < 4; kq++) wv[d4][kq] = wp[d4*4 + kq];

    for (int bb = 0; bb < EBT; bb++) {
        int b = bt*EBT + bb;
        __syncthreads();   // protect usm from previous iteration readers (also covers c1sm staging on bb==0)
        usm[t] = ((const float4*)(g_u + (size_t)b*ICAPS*CDIM))[t];
        __syncthreads();
        float4 uq0 = usm[i*4+0], uq1 = usm[i*4+1], uq2 = usm[i*4+2], uq3 = usm[i*4+3];
        float acc[4];
        #pragma unroll
        for (int d4 = 0; d4 < 4; d4++) {
            acc[d4] = wv[d4][0].x*uq0.x + wv[d4][0].y*uq0.y + wv[d4][0].z*uq0.z + wv[d4][0].w*uq0.w
                    + wv[d4][1].x*uq1.x + wv[d4][1].y*uq1.y + wv[d4][1].z*uq1.z + wv[d4][1].w*uq1.w
                    + wv[d4][2].x*uq2.x + wv[d4][2].y*uq2.y + wv[d4][2].z*uq2.z + wv[d4][2].w*uq2.w
                    + wv[d4][3].x*uq3.x + wv[d4][3].y*uq3.y + wv[d4][3].z*uq3.z + wv[d4][3].w*uq3.w;
        }
        // write u_hat[b,o,i,dq*4..+3] (fully coalesced across the block)
        *(float4*)&g_uhat[(((size_t)b*NCAPS + o)*ICAPS + i)*CDIM + dq*4] =
            make_float4(acc[0], acc[1], acc[2], acc[3]);
        // s1 partial: c1[o,i] * u_hat, reduced over i within warp (lanes stride 4)
        float c = c1sm[i];
        float4 sp = make_float4(acc[0]*c, acc[1]*c, acc[2]*c, acc[3]*c);
        #pragma unroll
        for (int off = 4; off <= 16; off <<= 1) {
            sp.x += __shfl_xor_sync(0xffffffffu, sp.x, off);
            sp.y += __shfl_xor_sync(0xffffffffu, sp.y, off);
            sp.z += __shfl_xor_sync(0xffffffffu, sp.z, off);
            sp.w += __shfl_xor_sync(0xffffffffu, sp.w, off);
        }
        if (lane < 4) s1p[warp][lane] = sp;   // lane == dq here
        __syncthreads();
        if (t < 4) {
            float4 s4 = s1p[0][t];
            #pragma unroll
            for (int wq = 1; wq < 12; wq++) {
                float4 q = s1p[wq][t];
                s4.x += q.x; s4.y += q.y; s4.z += q.z; s4.w += q.w;
            }
            float pn = s4.x*s4.x + s4.y*s4.y + s4.z*s4.z + s4.w*s4.w;
            pn += __shfl_xor_sync(0x0000000Fu, pn, 1);
            pn += __shfl_xor_sync(0x0000000Fu, pn, 2);
            float n = sqrtf(pn);
            float sc = (1.0f - expf(-n)) / (n + 1e-8f);
            vsm[t] = make_float4(s4.x*sc, s4.y*sc, s4.z*sc, s4.w*sc);
        }
        __syncthreads();
        float4 vq = vsm[dq];
        float dot = vq.x*acc[0] + vq.y*acc[1] + vq.z*acc[2] + vq.w*acc[3];
        dot += __shfl_xor_sync(0xffffffffu, dot, 1);
        dot += __shfl_xor_sync(0xffffffffu, dot, 2);
        if (dq == 0)
            g_blog[((size_t)b*NCAPS + o)*ICAPS + i] = cbsm[i] + dot;
    }
}

// per (b,i): online max + sumexp over the 181 out-caps (softmax axis=1)
__global__ void stats_kernel() {
    int b = blockIdx.x, i = threadIdx.x;  // 96 threads
    float m = -INFINITY, s = 0.f;
    for (int o = 0; o < NCAPS; o++) {
        float v = g_blog[(b*NCAPS + o)*ICAPS + i];
        if (v > m) { s = s * expf(m - v) + 1.f; m = v; }
        else       { s += expf(v - m); }
    }
    g_maxl[b*96 + i] = m;
    g_sume[b*96 + i] = s;
}

// one routing step for one (b,o): c -> weighted sum -> squash -> (b update | emit v,len)
__global__ void route_kernel(int last) {
    int o = blockIdx.x, b = blockIdx.y, t = threadIdx.x;  // 128 threads
    __shared__ float csm[96];
    __shared__ float oldl[96];
    __shared__ float uhsm[96*17];
    __shared__ float red[128];
    __shared__ float ssm[16];
    __shared__ float sc_sm, n_sm;
    if (t < 96) {
        float lv = g_blog[(b*NCAPS + o)*ICAPS + t];
        csm[t] = expf(lv - g_maxl[b*96 + t]) / g_sume[b*96 + t];
        oldl[t] = lv;
        const float4* uh = (const float4*)&g_uhat[(((size_t)b*NCAPS + o)*ICAPS + t)*CDIM];
        float4 q0 = uh[0], q1 = uh[1], q2 = uh[2], q3 = uh[3];
        float* dst = &uhsm[t*17];
        dst[0]=q0.x; dst[1]=q0.y; dst[2]=q0.z; dst[3]=q0.w;
        dst[4]=q1.x; dst[5]=q1.y; dst[6]=q1.z; dst[7]=q1.w;
        dst[8]=q2.x; dst[9]=q2.y; dst[10]=q2.z; dst[11]=q2.w;
        dst[12]=q3.x; dst[13]=q3.y; dst[14]=q3.z; dst[15]=q3.w;
    }
    __syncthreads();
    int k = t & 15, part = t >> 4;  // 8 partials per k
    float partial = 0.f;
    for (int i = part; i < 96; i += 8) partial += csm[i] * uhsm[i*17 + k];
    red[part*16 + k] = partial;
    __syncthreads();
    if (t < 16) {
        float s = 0.f;
        #pragma unroll
        for (int p = 0; p < 8; p++) s += red[p*16 + t];
        ssm[t] = s;
    }
    __syncthreads();
    if (t == 0) {
        float n2 = 0.f;
        #pragma unroll
        for (int kk = 0; kk < 16; kk++) n2 += ssm[kk]*ssm[kk];
        float n = sqrtf(n2);
        sc_sm = (1.0f - expf(-n)) / (n + 1e-8f);
        n_sm = n;
    }
    __syncthreads();
    if (!last) {
        if (t < 96) {
            float dot = 0.f;
            #pragma unroll
            for (int kk = 0; kk < 16; kk++) dot += ssm[kk] * uhsm[t*17 + kk];
            g_blog[(b*NCAPS + o)*ICAPS + t] = oldl[t] + sc_sm * dot;
        }
    } else {
        if (t < 16) g_x[(b*NCAPS + o)*CDIM + t] = ssm[t] * sc_sm;
        if (t == 0) g_len[b*NCAPS + o] = n_sm * sc_sm;
    }
}

// ---------------- peak picking ----------------------------------------------
__global__ void peak_kernel(float* __restrict__ out_len) {
    int b = blockIdx.x, t = threadIdx.x;  // 256 threads
    __shared__ float nl[NCAPS];
    __shared__ float pk[NCAPS];
    __shared__ float ssum;
    if (t < NCAPS) nl[t] = g_len[b*NCAPS + t];
    __syncthreads();
    if (t == 0) {
        float s = 0.f;
        for (int o = 0; o < NCAPS; o++) s += nl[o];
        ssum = s + 1e-8f;
    }
    __syncthreads();
    if (t < NCAPS) {
        float v = nl[t] / ssum;
        nl[t] = v;
        out_len[b*NCAPS + t] = v;
    }
    __syncthreads();
    if (t < NCAPS) {
        int lo = t - 5; if (lo < 0) lo = 0;
        int hi = t + 5; if (hi > NCAPS-1) hi = NCAPS-1;
        float m = -INFINITY;
        for (int j = lo; j <= hi; j++) m = fmaxf(m, nl[j]);
        pk[t] = (nl[t] == m) ? nl[t] : 0.f;
    }
    __syncthreads();
    if (t == 0) {
        int chosen[TOPK];
        for (int kk = 0; kk < TOPK; kk++) {
            float best = -INFINITY; int bi = 0;
            for (int j = 0; j < NCAPS; j++)
                if (pk[j] > best) { best = pk[j]; bi = j; }
            chosen[kk] = bi;
            pk[bi] = -INFINITY;
        }
        for (int a = 0; a < TOPK-1; a++)
            for (int c = 0; c < TOPK-1-a; c++)
                if (chosen[c] > chosen[c+1]) { int tmp = chosen[c]; chosen[c] = chosen[c+1]; chosen[c+1] = tmp; }
        for (int kk = 0; kk < TOPK; kk++) g_idx[b*TOPK + kk] = chosen[kk];
    }
}

// ---------------- MLP --------------------------------------------------------
// fc1 exploits one-hot sparsity: only rows [idx*16, idx*16+16) of fc1_w matter.
__global__ void fc1_kernel(const float* __restrict__ w, const float* __restrict__ bias) {
    int r = blockIdx.x, t = threadIdx.x;  // 256 threads, r in [0,2048)
    int b = r >> 2;
    int idx = g_idx[r];
    __shared__ float xf[16];
    if (t < 16) xf[t] = g_x[(b*NCAPS + idx)*CDIM + t];
    __syncthreads();
    for (int j = t; j < 1024; j += 256) {
        float acc = bias[j];
        #pragma unroll
        for (int d = 0; d < 16; d++) acc += xf[d] * w[(idx*16 + d)*1024 + j];
        g_f1[r*1024 + j] = gelu_exact(acc);
    }
}

// 128x64 tiled SGEMM: C = act(A[M,K] @ B[K,N] + bias). M%128==0, N%64==0, K%16==0.
// trans_head: scatter-store as W_out[b, a, kk] instead of row-major C.
__global__ void sgemm_kernel(const float* __restrict__ A, const float* __restrict__ Bw,
                             const float* __restrict__ bias, float* __restrict__ C,
                             int M, int N, int K, int apply_gelu, int trans_head) {
    __shared__ float As[16][132];
    __shared__ float Bs[16][68];
    int tid = threadIdx.x;                  // 256 threads
    int tm = tid >> 4, tn = tid & 15;
    int rowBase = blockIdx.y * 128;
    int colBase = blockIdx.x * 64;
    float acc[8][4];
    {
        float bv[4];
        #pragma unroll
        for (int j = 0; j < 4; j++) bv[j] = bias[colBase + tn*4 + j];
        #pragma unroll
        for (int i = 0; i < 8; i++)
            #pragma unroll
            for (int j = 0; j < 4; j++) acc[i][j] = bv[j];
    }
    int arow = tid >> 1, ak = (tid & 1) * 8;
    int brow = tid >> 4, bcol = (tid & 15) * 4;
    for (int k0 = 0; k0 < K; k0 += 16) {
        const float* ap = &A[(size_t)(rowBase + arow)*K + k0 + ak];
        float4 a0 = *(const float4*)ap;
        float4 a1 = *(const float4*)(ap + 4);
        As[ak+0][arow] = a0.x; As[ak+1][arow] = a0.y; As[ak+2][arow] = a0.z; As[ak+3][arow] = a0.w;
        As[ak+4][arow] = a1.x; As[ak+5][arow] = a1.y; As[ak+6][arow] = a1.z; As[ak+7][arow] = a1.w;
        float4 bv = *(const float4*)&Bw[(size_t)(k0 + brow)*N + colBase + bcol];
        *(float4*)&Bs[brow][bcol] = bv;
        __syncthreads();
        #pragma unroll
        for (int kk = 0; kk < 16; kk++) {
            float4 b4 = *(const float4*)&Bs[kk][tn*4];
            float4 a4 = *(const float4*)&As[kk][tm*8];
            float4 a5 = *(const float4*)&As[kk][tm*8+4];
            acc[0][0] += a4.x*b4.x; acc[0][1] += a4.x*b4.y; acc[0][2] += a4.x*b4.z; acc[0][3] += a4.x*b4.w;
            acc[1][0] += a4.y*b4.x; acc[1][1] += a4.y*b4.y; acc[1][2] += a4.y*b4.z; acc[1][3] += a4.y*b4.w;
            acc[2][0] += a4.z*b4.x; acc[2][1] += a4.z*b4.y; acc[2][2] += a4.z*b4.z; acc[2][3] += a4.z*b4.w;
            acc[3][0] += a4.w*b4.x; acc[3][1] += a4.w*b4.y; acc[3][2] += a4.w*b4.z; acc[3][3] += a4.w*b4.w;
            acc[4][0] += a5.x*b4.x; acc[4][1] += a5.x*b4.y; acc[4][2] += a5.x*b4.z; acc[4][3] += a5.x*b4.w;
            acc[5][0] += a5.y*b4.x; acc[5][1] += a5.y*b4.y; acc[5][2] += a5.y*b4.z; acc[5][3] += a5.y*b4.w;
            acc[6][0] += a5.z*b4.x; acc[6][1] += a5.z*b4.y; acc[6][2] += a5.z*b4.z; acc[6][3] += a5.z*b4.w;
            acc[7][0] += a5.w*b4.x; acc[7][1] += a5.w*b4.y; acc[7][2] += a5.w*b4.z; acc[7][3] += a5.w*b4.w;
        }
        __syncthreads();
    }
    #pragma unroll
    for (int i = 0; i < 8; i++) {
        int r = rowBase + tm*8 + i;
        #pragma unroll
        for (int j = 0; j < 4; j++) {
            int n = colBase + tn*4 + j;
            float v = acc[i][j];
            if (apply_gelu) v = gelu_exact(v);
            if (!trans_head) C[(size_t)r*N + n] = v;
            else {
                int b = r >> 2, kk = r & 3;
                C[(b*A2 + n)*TOPK + kk] = v;   // W_out[b, a, k]
            }
        }
    }
}

// ---------------- launcher ---------------------------------------------------
extern "C" void kernel_launch(void* const* d_in, const int* in_sizes, int n_in,
                              void* d_out, int out_size) {
    const float* scm     = (const float*)d_in[0];
    const float* conv1_w = (const float*)d_in[2];
    const float* conv1_b = (const float*)d_in[3];
    const float* conv2_w = (const float*)d_in[4];
    const float* conv2_b = (const float*)d_in[5];
    const float* conv3_w = (const float*)d_in[6];
    const float* conv3_b = (const float*)d_in[7];
    const float* pc_w    = (const float*)d_in[8];
    const float* pc_b    = (const float*)d_in[9];
    const float* caps_W  = (const float*)d_in[10];
    const float* caps_b  = (const float*)d_in[11];
    const float* fc1_w   = (const float*)d_in[12];
    const float* fc1_b   = (const float*)d_in[13];
    const float* fc2_w   = (const float*)d_in[14];
    const float* fc2_b   = (const float*)d_in[15];
    const float* fc3_w   = (const float*)d_in[16];
    const float* fc3_b   = (const float*)d_in[17];
    const float* fc4_w   = (const float*)d_in[18];
    const float* fc4_b   = (const float*)d_in[19];
    const float* fc5_w   = (const float*)d_in[20];
    const float* fc5_b   = (const float*)d_in[21];
    const float* head_w  = (const float*)d_in[22];
    const float* head_b  = (const float*)d_in[23];
    float* out = (float*)d_out;

    // conv stack
    conv1_kernel<<<BATCH, 256>>>(scm, conv1_w, conv1_b);
    conv2_kernel<<<BATCH/2, 256>>>(conv2_w, conv2_b);
    conv3_kernel<<<BATCH, 256>>>(conv3_w, conv3_b);
    pc_kernel<<<BATCH, 192>>>(pc_w, pc_b);

    // capsule layer: c1 precompute, fused einsum+iter1, then iterations 2 and 3
    c1_kernel<<<1, 96>>>(caps_b);
    einsum_iter1_kernel<<<dim3(NCAPS, BATCH/EBT), 384>>>(caps_W, caps_b);
    stats_kernel<<<BATCH, 96>>>();
    route_kernel<<<dim3(NCAPS, BATCH), 128>>>(0);   // iteration 2 (b update)
    stats_kernel<<<BATCH, 96>>>();
    route_kernel<<<dim3(NCAPS, BATCH), 128>>>(1);   // iteration 3 (emit v, len)

    // peaks + length output (length lives after W_out in d_out)
    float* out_len = out + BATCH * A2 * TOPK;
    peak_kernel<<<BATCH, 256>>>(out_len);

    // MLP
    float* g_f1p; cudaGetSymbolAddress((void**)&g_f1p, g_f1);
    float* g_f2p; cudaGetSymbolAddress((void**)&g_f2p, g_f2);
    float* g_f3p; cudaGetSymbolAddress((void**)&g_f3p, g_f3);
    float* g_f4p; cudaGetSymbolAddress((void**)&g_f4p, g_f4);
    float* g_f5p; cudaGetSymbolAddress((void**)&g_f5p, g_f5);

    fc1_kernel<<<MLPM, 256>>>(fc1_w, fc1_b);
    sgemm_kernel<<<dim3(768/64, MLPM/128), 256>>>(g_f1p, fc2_w, fc2_b, g_f2p, MLPM, 768, 1024, 1, 0);
    sgemm_kernel<<<dim3(512/64, MLPM/128), 256>>>(g_f2p, fc3_w, fc3_b, g_f3p, MLPM, 512,  768, 1, 0);
    sgemm_kernel<<<dim3(512/64, MLPM/128), 256>>>(g_f3p, fc4_w, fc4_b, g_f4p, MLPM, 512,  512, 1, 0);
    sgemm_kernel<<<dim3(256/64, MLPM/128), 256>>>(g_f4p, fc5_w, fc5_b, g_f5p, MLPM, 256,  512, 1, 0);
    sgemm_kernel<<<dim3(128/64, MLPM/128), 256>>>(g_f5p, head_w, head_b, out,  MLPM, 128,  256, 0, 1);
    (void)in_sizes; (void)n_in; (void)out_size;
}

// round 10
// speedup vs baseline: 1.0380x; 1.0380x over previous
#include <cuda_runtime.h>
#include <math.h>

// Problem constants (setup_inputs is deterministic: B=512, K=4)
#define BATCH 512
#define TOPK 4
#define NCAPS 181
#define ICAPS 96
#define CDIM 16
#define A2 128           // 2 * num_antennas
#define MLPM (BATCH*TOPK) // 2048

// ---------------- scratch (device globals; no runtime allocation) -----------
__device__ float g_h1[BATCH*64*49];          // conv1 out
__device__ float g_h2[BATCH*128*36];         // conv2 out
__device__ float g_h3[BATCH*256*25];         // conv3 out
__device__ float g_u [BATCH*ICAPS*CDIM];     // squashed primary caps
__device__ float g_c1[NCAPS*ICAPS];          // iter-1 coupling (batch-independent)
__device__ float g_blog[BATCH*NCAPS*ICAPS];  // routing logits
__device__ float g_maxl[BATCH*ICAPS];
__device__ float g_sume[BATCH*ICAPS];
__device__ float g_x  [BATCH*NCAPS*CDIM];    // final v
__device__ float g_len[BATCH*NCAPS];         // unnormalized lengths
__device__ int   g_idx[BATCH*TOPK];
__device__ float g_f1[MLPM*1024];
__device__ float g_f2[MLPM*768];
__device__ float g_f3[MLPM*512];
__device__ float g_f4[MLPM*512];
__device__ float g_f5[MLPM*256];

__device__ __forceinline__ float gelu_exact(float v) {
    return 0.5f * v * (1.0f + erff(v * 0.70710678118654752440f));
}

// ---------------- conv stack -------------------------------------------------
__global__ void conv1_kernel(const float* __restrict__ x, const float* __restrict__ w,
                             const float* __restrict__ bias) {
    int b = blockIdx.x, t = threadIdx.x;
    __shared__ float ins[192];   // 3x8x8
    __shared__ float ws[768];    // 64x3x2x2
    if (t < 192) ins[t] = x[b*192 + t];
    for (int j = t; j < 768; j += 256) ws[j] = w[j];
    __syncthreads();
    for (int p = t; p < 64*49; p += 256) {
        int oc = p / 49, pos = p % 49, y = pos / 7, xx = pos % 7;
        float acc = bias[oc];
        #pragma unroll
        for (int ic = 0; ic < 3; ic++)
            #pragma unroll
            for (int ky = 0; ky < 2; ky++)
                #pragma unroll
                for (int kx = 0; kx < 2; kx++)
                    acc += ws[((oc*3+ic)*2+ky)*2+kx] * ins[ic*64 + (y+ky)*8 + xx+kx];
        g_h1[b*3136 + p] = gelu_exact(acc);
    }
}

// conv2: [B,64,7,7] -> [B,128,6,6]. One out-channel per thread, 2 images/block.
__global__ void conv2_kernel(const float* __restrict__ w, const float* __restrict__ bias) {
    int b0 = blockIdx.x * 2, t = threadIdx.x;       // 256 threads
    int img = t >> 7, oc = t & 127;
    __shared__ float ins[2][64*49];                 // 25.1 KB
    for (int j = t; j < 2*64*49; j += 256) ins[j/3136][j%3136] = g_h1[b0*3136 + j];
    __syncthreads();
    const float* inp = ins[img];
    float acc[36];
    {
        float bv = bias[oc];
        #pragma unroll
        for (int p = 0; p < 36; p++) acc[p] = bv;
    }
    const float4* wp4 = (const float4*)(w + oc*256);
    for (int ic = 0; ic < 64; ic++) {
        float4 wv = wp4[ic];
        const float* r = &inp[ic*49];
        #pragma unroll
        for (int y = 0; y < 6; y++)
            #pragma unroll
            for (int xx = 0; xx < 6; xx++)
                acc[y*6+xx] += wv.x*r[y*7+xx] + wv.y*r[y*7+xx+1]
                             + wv.z*r[y*7+xx+7] + wv.w*r[y*7+xx+8];
    }
    float* outp = &g_h2[(b0+img)*4608 + oc*36];
    #pragma unroll
    for (int p = 0; p < 36; p++) outp[p] = gelu_exact(acc[p]);
}

// conv3: [B,128,6,6] -> [B,256,5,5]. One out-channel per thread, 1 image/block.
__global__ void conv3_kernel(const float* __restrict__ w, const float* __restrict__ bias) {
    int b = blockIdx.x, oc = threadIdx.x;           // 256 threads
    __shared__ float ins[128*36];                   // 18 KB
    for (int j = oc; j < 128*36; j += 256) ins[j] = g_h2[b*4608 + j];
    __syncthreads();
    float acc[25];
    {
        float bv = bias[oc];
        #pragma unroll
        for (int p = 0; p < 25; p++) acc[p] = bv;
    }
    const float4* wp4 = (const float4*)(w + oc*512);
    for (int ic = 0; ic < 128; ic++) {
        float4 wv = wp4[ic];
        const float* r = &ins[ic*36];
        #pragma unroll
        for (int y = 0; y < 5; y++)
            #pragma unroll
            for (int xx = 0; xx < 5; xx++)
                acc[y*5+xx] += wv.x*r[y*6+xx] + wv.y*r[y*6+xx+1]
                             + wv.z*r[y*6+xx+6] + wv.w*r[y*6+xx+7];
    }
    float* outp = &g_h3[b*6400 + oc*25];
    #pragma unroll
    for (int p = 0; p < 25; p++) outp[p] = gelu_exact(acc[p]);
}

// primary caps: [B,256,5,5] -> [B,96,16] + squash. One caps-channel per thread, 1 img/block.
// (96-thread version — the 192-thread split doubled weight LDG traffic and regressed.)
__global__ void pc_kernel(const float* __restrict__ w, const float* __restrict__ bias) {
    int b = blockIdx.x, oc = threadIdx.x;           // 96 threads
    __shared__ float ins[256*25];                   // 25.6 KB
    for (int j = oc; j < 256*25; j += 96) ins[j] = g_h3[b*6400 + j];
    __syncthreads();
    float acc[16];
    {
        float bv = bias[oc];
        #pragma unroll
        for (int p = 0; p < 16; p++) acc[p] = bv;
    }
    const float4* wp4 = (const float4*)(w + oc*1024);
    for (int ic = 0; ic < 256; ic++) {
        float4 wv = wp4[ic];
        const float* r = &ins[ic*25];
        #pragma unroll
        for (int y = 0; y < 4; y++)
            #pragma unroll
            for (int xx = 0; xx < 4; xx++)
                acc[y*4+xx] += wv.x*r[y*5+xx] + wv.y*r[y*5+xx+1]
                             + wv.z*r[y*5+xx+5] + wv.w*r[y*5+xx+6];
    }
    float n2 = 0.f;
    #pragma unroll
    for (int d = 0; d < 16; d++) n2 += acc[d]*acc[d];
    float n = sqrtf(n2);
    float sc = (1.0f - expf(-n)) / (n + 1e-8f);
    float* outp = &g_u[(b*96 + oc)*16];
    #pragma unroll
    for (int d = 0; d < 16; d++) outp[d] = acc[d] * sc;
}

// ---------------- capsule layer (u_hat never materialized) -------------------
// c1[o,i] = softmax over o of caps_b (batch-independent)
__global__ void c1_kernel(const float* __restrict__ caps_b) {
    int i = threadIdx.x;   // 96 threads, 1 block
    float m = -INFINITY;
    for (int o = 0; o < NCAPS; o++) m = fmaxf(m, caps_b[o*ICAPS + i]);
    float s = 0.f;
    for (int o = 0; o < NCAPS; o++) s += expf(caps_b[o*ICAPS + i] - m);
    for (int o = 0; o < NCAPS; o++)
        g_c1[o*ICAPS + i] = expf(caps_b[o*ICAPS + i] - m) / s;
}

// One routing iteration with on-the-fly u_hat recompute.
// Grid (NCAPS, 4), 384 threads. Thread (i=t>>2, dq=t&3) holds W[o,i,dq*4..+3,:] in
// registers. Per round: 4 batch elements, u staged in smem, û recomputed, then
// c-weighted sum -> squash -> (blog update | emit x,len).
// mode: 0 = iter1 (c from g_c1, blog = caps_b + v·û)
//       1 = iter2 (c from softmax(blog), blog += v·û)
//       2 = iter3 (c from softmax(blog), emit x = v, len = |v|)
__global__ __launch_bounds__(384) void caps_iter_kernel(
        const float* __restrict__ W, const float* __restrict__ caps_b, int mode) {
    int o = blockIdx.x, bt = blockIdx.y;
    int t = threadIdx.x;
    int i = t >> 2, dq = t & 3;
    int lane = t & 31, warp = t >> 5;
    __shared__ float4 usm[4][384];      // 4 b's of u : 24.6 KB
    __shared__ float csm[4][96];
    __shared__ float olsm[4][96];
    __shared__ float c1sm[96], cbsm[96];
    __shared__ float4 s1p[12][16];      // [warp][bb*4+dq]
    __shared__ float vsm[4][16];        // squashed v per bb
    __shared__ float nsm[4];            // |v| per bb
    if (mode == 0 && t < 96) {
        c1sm[t] = g_c1[o*ICAPS + t];
        cbsm[t] = caps_b[o*ICAPS + t];
    }
    // W[o, i, dq*4+d4, :] into registers (64 floats)
    float4 wv[4][4];
    const float4* wp = (const float4*)(W + ((size_t)(o*ICAPS + i)*CDIM + dq*4)*CDIM);
    #pragma unroll
    for (int d4 = 0; d4 < 4; d4++)
        #pragma unroll
        for (int kq = 0; kq < 4; kq++) wv[d4][kq] = wp[d4*4 + kq];

    for (int r = 0; r < 32; r++) {
        int b0 = bt*128 + r*4;
        __syncthreads();   // protect smem from previous round's readers (covers c1sm on r==0)
        #pragma unroll
        for (int bb = 0; bb < 4; bb++)
            usm[bb][t] = ((const float4*)(g_u + (size_t)(b0+bb)*ICAPS*CDIM))[t];
        if (mode != 0) {
            int bb = t / 96, ii = t - bb*96;
            int b = b0 + bb;
            float lv = g_blog[((size_t)b*NCAPS + o)*ICAPS + ii];
            csm[bb][ii] = expf(lv - g_maxl[b*96 + ii]) / g_sume[b*96 + ii];
            olsm[bb][ii] = lv;
        }
        __syncthreads();
        // recompute u_hat slices: acc[bb][d4] for d = dq*4+d4
        float acc[4][4];
        #pragma unroll
        for (int bb = 0; bb < 4; bb++) {
            float4 uq0 = usm[bb][i*4+0], uq1 = usm[bb][i*4+1];
            float4 uq2 = usm[bb][i*4+2], uq3 = usm[bb][i*4+3];
            #pragma unroll
            for (int d4 = 0; d4 < 4; d4++) {
                acc[bb][d4] =
                      wv[d4][0].x*uq0.x + wv[d4][0].y*uq0.y + wv[d4][0].z*uq0.z + wv[d4][0].w*uq0.w
                    + wv[d4][1].x*uq1.x + wv[d4][1].y*uq1.y + wv[d4][1].z*uq1.z + wv[d4][1].w*uq1.w
                    + wv[d4][2].x*uq2.x + wv[d4][2].y*uq2.y + wv[d4][2].z*uq2.z + wv[d4][2].w*uq2.w
                    + wv[d4][3].x*uq3.x + wv[d4][3].y*uq3.y + wv[d4][3].z*uq3.z + wv[d4][3].w*uq3.w;
            }
        }
        // c-weighted partial sums, warp-reduced over this warp's 8 i values
        #pragma unroll
        for (int bb = 0; bb < 4; bb++) {
            float c = (mode == 0) ? c1sm[i] : csm[bb][i];
            float4 sp = make_float4(acc[bb][0]*c, acc[bb][1]*c, acc[bb][2]*c, acc[bb][3]*c);
            #pragma unroll
            for (int off = 4; off <= 16; off <<= 1) {
                sp.x += __shfl_xor_sync(0xffffffffu, sp.x, off);
                sp.y += __shfl_xor_sync(0xffffffffu, sp.y, off);
                sp.z += __shfl_xor_sync(0xffffffffu, sp.z, off);
                sp.w += __shfl_xor_sync(0xffffffffu, sp.w, off);
            }
            if (lane < 4) s1p[warp][bb*4 + lane] = sp;   // lane == dq
        }
        __syncthreads();
        if (t < 16) {   // t = bb*4 + dq
            int bb = t >> 2;
            float4 s4 = s1p[0][t];
            #pragma unroll
            for (int wq = 1; wq < 12; wq++) {
                float4 q = s1p[wq][t];
                s4.x += q.x; s4.y += q.y; s4.z += q.z; s4.w += q.w;
            }
            float pn = s4.x*s4.x + s4.y*s4.y + s4.z*s4.z + s4.w*s4.w;
            pn += __shfl_xor_sync(0x0000ffffu, pn, 1);
            pn += __shfl_xor_sync(0x0000ffffu, pn, 2);
            float n = sqrtf(pn);
            float sc = (1.0f - expf(-n)) / (n + 1e-8f);
            int d0 = (t & 3) * 4;
            vsm[bb][d0+0] = s4.x*sc; vsm[bb][d0+1] = s4.y*sc;
            vsm[bb][d0+2] = s4.z*sc; vsm[bb][d0+3] = s4.w*sc;
            if ((t & 3) == 0) nsm[bb] = n * sc;
        }
        __syncthreads();
        if (mode == 2) {
            if (t < 64) {
                int bb = t >> 4, d = t & 15;
                g_x[((size_t)(b0+bb)*NCAPS + o)*CDIM + d] = vsm[bb][d];
            }
            if (t < 4) g_len[(b0+t)*NCAPS + o] = nsm[t];
        } else {
            #pragma unroll
            for (int bb = 0; bb < 4; bb++) {
                float dot = vsm[bb][dq*4+0]*acc[bb][0] + vsm[bb][dq*4+1]*acc[bb][1]
                          + vsm[bb][dq*4+2]*acc[bb][2] + vsm[bb][dq*4+3]*acc[bb][3];
                dot += __shfl_xor_sync(0xffffffffu, dot, 1);
                dot += __shfl_xor_sync(0xffffffffu, dot, 2);
                if (dq == 0) {
                    float base = (mode == 0) ? cbsm[i] : olsm[bb][i];
                    g_blog[((size_t)(b0+bb)*NCAPS + o)*ICAPS + i] = base + dot;
                }
            }
        }
    }
}

// per (b,i): online max + sumexp over the 181 out-caps (softmax axis=1)
__global__ void stats_kernel() {
    int b = blockIdx.x, i = threadIdx.x;  // 96 threads
    float m = -INFINITY, s = 0.f;
    for (int o = 0; o < NCAPS; o++) {
        float v = g_blog[(b*NCAPS + o)*ICAPS + i];
        if (v > m) { s = s * expf(m - v) + 1.f; m = v; }
        else       { s += expf(v - m); }
    }
    g_maxl[b*96 + i] = m;
    g_sume[b*96 + i] = s;
}

// ---------------- peak picking ----------------------------------------------
__global__ void peak_kernel(float* __restrict__ out_len) {
    int b = blockIdx.x, t = threadIdx.x;  // 256 threads
    __shared__ float nl[NCAPS];
    __shared__ float pk[NCAPS];
    __shared__ float ssum;
    if (t < NCAPS) nl[t] = g_len[b*NCAPS + t];
    __syncthreads();
    if (t == 0) {
        float s = 0.f;
        for (int o = 0; o < NCAPS; o++) s += nl[o];
        ssum = s + 1e-8f;
    }
    __syncthreads();
    if (t < NCAPS) {
        float v = nl[t] / ssum;
        nl[t] = v;
        out_len[b*NCAPS + t] = v;
    }
    __syncthreads();
    if (t < NCAPS) {
        int lo = t - 5; if (lo < 0) lo = 0;
        int hi = t + 5; if (hi > NCAPS-1) hi = NCAPS-1;
        float m = -INFINITY;
        for (int j = lo; j <= hi; j++) m = fmaxf(m, nl[j]);
        pk[t] = (nl[t] == m) ? nl[t] : 0.f;
    }
    __syncthreads();
    if (t == 0) {
        int chosen[TOPK];
        for (int kk = 0; kk < TOPK; kk++) {
            float best = -INFINITY; int bi = 0;
            for (int j = 0; j < NCAPS; j++)
                if (pk[j] > best) { best = pk[j]; bi = j; }
            chosen[kk] = bi;
            pk[bi] = -INFINITY;
        }
        for (int a = 0; a < TOPK-1; a++)
            for (int c = 0; c < TOPK-1-a; c++)
                if (chosen[c] > chosen[c+1]) { int tmp = chosen[c]; chosen[c] = chosen[c+1]; chosen[c+1] = tmp; }
        for (int kk = 0; kk < TOPK; kk++) g_idx[b*TOPK + kk] = chosen[kk];
    }
}

// ---------------- MLP --------------------------------------------------------
// fc1 exploits one-hot sparsity: only rows [idx*16, idx*16+16) of fc1_w matter.
__global__ void fc1_kernel(const float* __restrict__ w, const float* __restrict__ bias) {
    int r = blockIdx.x, t = threadIdx.x;  // 256 threads, r in [0,2048)
    int b = r >> 2;
    int idx = g_idx[r];
    __shared__ float xf[16];
    if (t < 16) xf[t] = g_x[(b*NCAPS + idx)*CDIM + t];
    __syncthreads();
    for (int j = t; j < 1024; j += 256) {
        float acc = bias[j];
        #pragma unroll
        for (int d = 0; d < 16; d++) acc += xf[d] * w[(idx*16 + d)*1024 + j];
        g_f1[r*1024 + j] = gelu_exact(acc);
    }
}

// 128x64 tiled SGEMM: C = act(A[M,K] @ B[K,N] + bias). M%128==0, N%64==0, K%16==0.
// trans_head: scatter-store as W_out[b, a, kk] instead of row-major C.
__global__ void sgemm_kernel(const float* __restrict__ A, const float* __restrict__ Bw,
                             const float* __restrict__ bias, float* __restrict__ C,
                             int M, int N, int K, int apply_gelu, int trans_head) {
    __shared__ float As[16][132];
    __shared__ float Bs[16][68];
    int tid = threadIdx.x;                  // 256 threads
    int tm = tid >> 4, tn = tid & 15;
    int rowBase = blockIdx.y * 128;
    int colBase = blockIdx.x * 64;
    float acc[8][4];
    {
        float bv[4];
        #pragma unroll
        for (int j = 0; j < 4; j++) bv[j] = bias[colBase + tn*4 + j];
        #pragma unroll
        for (int i = 0; i < 8; i++)
            #pragma unroll
            for (int j = 0; j < 4; j++) acc[i][j] = bv[j];
    }
    int arow = tid >> 1, ak = (tid & 1) * 8;
    int brow = tid >> 4, bcol = (tid & 15) * 4;
    for (int k0 = 0; k0 < K; k0 += 16) {
        const float* ap = &A[(size_t)(rowBase + arow)*K + k0 + ak];
        float4 a0 = *(const float4*)ap;
        float4 a1 = *(const float4*)(ap + 4);
        As[ak+0][arow] = a0.x; As[ak+1][arow] = a0.y; As[ak+2][arow] = a0.z; As[ak+3][arow] = a0.w;
        As[ak+4][arow] = a1.x; As[ak+5][arow] = a1.y; As[ak+6][arow] = a1.z; As[ak+7][arow] = a1.w;
        float4 bv = *(const float4*)&Bw[(size_t)(k0 + brow)*N + colBase + bcol];
        *(float4*)&Bs[brow][bcol] = bv;
        __syncthreads();
        #pragma unroll
        for (int kk = 0; kk < 16; kk++) {
            float4 b4 = *(const float4*)&Bs[kk][tn*4];
            float4 a4 = *(const float4*)&As[kk][tm*8];
            float4 a5 = *(const float4*)&As[kk][tm*8+4];
            acc[0][0] += a4.x*b4.x; acc[0][1] += a4.x*b4.y; acc[0][2] += a4.x*b4.z; acc[0][3] += a4.x*b4.w;
            acc[1][0] += a4.y*b4.x; acc[1][1] += a4.y*b4.y; acc[1][2] += a4.y*b4.z; acc[1][3] += a4.y*b4.w;
            acc[2][0] += a4.z*b4.x; acc[2][1] += a4.z*b4.y; acc[2][2] += a4.z*b4.z; acc[2][3] += a4.z*b4.w;
            acc[3][0] += a4.w*b4.x; acc[3][1] += a4.w*b4.y; acc[3][2] += a4.w*b4.z; acc[3][3] += a4.w*b4.w;
            acc[4][0] += a5.x*b4.x; acc[4][1] += a5.x*b4.y; acc[4][2] += a5.x*b4.z; acc[4][3] += a5.x*b4.w;
            acc[5][0] += a5.y*b4.x; acc[5][1] += a5.y*b4.y; acc[5][2] += a5.y*b4.z; acc[5][3] += a5.y*b4.w;
            acc[6][0] += a5.z*b4.x; acc[6][1] += a5.z*b4.y; acc[6][2] += a5.z*b4.z; acc[6][3] += a5.z*b4.w;
            acc[7][0] += a5.w*b4.x; acc[7][1] += a5.w*b4.y; acc[7][2] += a5.w*b4.z; acc[7][3] += a5.w*b4.w;
        }
        __syncthreads();
    }
    #pragma unroll
    for (int i = 0; i < 8; i++) {
        int r = rowBase + tm*8 + i;
        #pragma unroll
        for (int j = 0; j < 4; j++) {
            int n = colBase + tn*4 + j;
            float v = acc[i][j];
            if (apply_gelu) v = gelu_exact(v);
            if (!trans_head) C[(size_t)r*N + n] = v;
            else {
                int b = r >> 2, kk = r & 3;
                C[(b*A2 + n)*TOPK + kk] = v;   // W_out[b, a, k]
            }
        }
    }
}

// ---------------- launcher ---------------------------------------------------
extern "C" void kernel_launch(void* const* d_in, const int* in_sizes, int n_in,
                              void* d_out, int out_size) {
    const float* scm     = (const float*)d_in[0];
    const float* conv1_w = (const float*)d_in[2];
    const float* conv1_b = (const float*)d_in[3];
    const float* conv2_w = (const float*)d_in[4];
    const float* conv2_b = (const float*)d_in[5];
    const float* conv3_w = (const float*)d_in[6];
    const float* conv3_b = (const float*)d_in[7];
    const float* pc_w    = (const float*)d_in[8];
    const float* pc_b    = (const float*)d_in[9];
    const float* caps_W  = (const float*)d_in[10];
    const float* caps_b  = (const float*)d_in[11];
    const float* fc1_w   = (const float*)d_in[12];
    const float* fc1_b   = (const float*)d_in[13];
    const float* fc2_w   = (const float*)d_in[14];
    const float* fc2_b   = (const float*)d_in[15];
    const float* fc3_w   = (const float*)d_in[16];
    const float* fc3_b   = (const float*)d_in[17];
    const float* fc4_w   = (const float*)d_in[18];
    const float* fc4_b   = (const float*)d_in[19];
    const float* fc5_w   = (const float*)d_in[20];
    const float* fc5_b   = (const float*)d_in[21];
    const float* head_w  = (const float*)d_in[22];
    const float* head_b  = (const float*)d_in[23];
    float* out = (float*)d_out;

    // conv stack
    conv1_kernel<<<BATCH, 256>>>(scm, conv1_w, conv1_b);
    conv2_kernel<<<BATCH/2, 256>>>(conv2_w, conv2_b);
    conv3_kernel<<<BATCH, 256>>>(conv3_w, conv3_b);
    pc_kernel<<<BATCH, 96>>>(pc_w, pc_b);

    // capsule routing with on-the-fly u_hat recompute (u_hat never stored)
    c1_kernel<<<1, 96>>>(caps_b);
    caps_iter_kernel<<<dim3(NCAPS, BATCH/128), 384>>>(caps_W, caps_b, 0);
    stats_kernel<<<BATCH, 96>>>();
    caps_iter_kernel<<<dim3(NCAPS, BATCH/128), 384>>>(caps_W, caps_b, 1);
    stats_kernel<<<BATCH, 96>>>();
    caps_iter_kernel<<<dim3(NCAPS, BATCH/128), 384>>>(caps_W, caps_b, 2);

    // peaks + length output (length lives after W_out in d_out)
    float* out_len = out + BATCH * A2 * TOPK;
    peak_kernel<<<BATCH, 256>>>(out_len);

    // MLP
    float* g_f1p; cudaGetSymbolAddress((void**)&g_f1p, g_f1);
    float* g_f2p; cudaGetSymbolAddress((void**)&g_f2p, g_f2);
    float* g_f3p; cudaGetSymbolAddress((void**)&g_f3p, g_f3);
    float* g_f4p; cudaGetSymbolAddress((void**)&g_f4p, g_f4);
    float* g_f5p; cudaGetSymbolAddress((void**)&g_f5p, g_f5);

    fc1_kernel<<<MLPM, 256>>>(fc1_w, fc1_b);
    sgemm_kernel<<<dim3(768/64, MLPM/128), 256>>>(g_f1p, fc2_w, fc2_b, g_f2p, MLPM, 768, 1024, 1, 0);
    sgemm_kernel<<<dim3(512/64, MLPM/128), 256>>>(g_f2p, fc3_w, fc3_b, g_f3p, MLPM, 512,  768, 1, 0);
    sgemm_kernel<<<dim3(512/64, MLPM/128), 256>>>(g_f3p, fc4_w, fc4_b, g_f4p, MLPM, 512,  512, 1, 0);
    sgemm_kernel<<<dim3(256/64, MLPM/128), 256>>>(g_f4p, fc5_w, fc5_b, g_f5p, MLPM, 256,  512, 1, 0);
    sgemm_kernel<<<dim3(128/64, MLPM/128), 256>>>(g_f5p, head_w, head_b, out,  MLPM, 128,  256, 0, 1);
    (void)in_sizes; (void)n_in; (void)out_size;
}

// round 11
// speedup vs baseline: 1.2353x; 1.1900x over previous
#include <cuda_runtime.h>
#include <math.h>

// Problem constants (setup_inputs is deterministic: B=512, K=4)
#define BATCH 512
#define TOPK 4
#define NCAPS 181
#define ICAPS 96
#define CDIM 16
#define A2 128           // 2 * num_antennas
#define MLPM (BATCH*TOPK) // 2048

// ---------------- scratch (device globals; no runtime allocation) -----------
__device__ float g_h1[BATCH*64*49];          // conv1 out
__device__ float g_h2[BATCH*128*36];         // conv2 out
__device__ float g_h3[BATCH*256*25];         // conv3 out
__device__ float g_u [BATCH*ICAPS*CDIM];     // squashed primary caps
__device__ float g_uhat[(size_t)NCAPS*BATCH*ICAPS*CDIM]; // 569 MB, layout [o][b][i][d]
__device__ float g_c1[NCAPS*ICAPS];          // iter-1 coupling (batch-independent)
__device__ float g_blog[BATCH*NCAPS*ICAPS];  // routing logits
__device__ float g_maxl[BATCH*ICAPS];
__device__ float g_sume[BATCH*ICAPS];
__device__ float g_x  [BATCH*NCAPS*CDIM];    // final v
__device__ float g_len[BATCH*NCAPS];         // unnormalized lengths
__device__ int   g_idx[BATCH*TOPK];
__device__ float g_f1[MLPM*1024];
__device__ float g_f2[MLPM*768];
__device__ float g_f3[MLPM*512];
__device__ float g_f4[MLPM*512];
__device__ float g_f5[MLPM*256];

__device__ __forceinline__ float gelu_exact(float v) {
    return 0.5f * v * (1.0f + erff(v * 0.70710678118654752440f));
}

// ---------------- conv stack -------------------------------------------------
__global__ void conv1_kernel(const float* __restrict__ x, const float* __restrict__ w,
                             const float* __restrict__ bias) {
    int b = blockIdx.x, t = threadIdx.x;
    __shared__ float ins[192];   // 3x8x8
    __shared__ float ws[768];    // 64x3x2x2
    if (t < 192) ins[t] = x[b*192 + t];
    for (int j = t; j < 768; j += 256) ws[j] = w[j];
    __syncthreads();
    for (int p = t; p < 64*49; p += 256) {
        int oc = p / 49, pos = p % 49, y = pos / 7, xx = pos % 7;
        float acc = bias[oc];
        #pragma unroll
        for (int ic = 0; ic < 3; ic++)
            #pragma unroll
            for (int ky = 0; ky < 2; ky++)
                #pragma unroll
                for (int kx = 0; kx < 2; kx++)
                    acc += ws[((oc*3+ic)*2+ky)*2+kx] * ins[ic*64 + (y+ky)*8 + xx+kx];
        g_h1[b*3136 + p] = gelu_exact(acc);
    }
}

// conv2: [B,64,7,7] -> [B,128,6,6]. One out-channel per thread, 2 images/block.
__global__ void conv2_kernel(const float* __restrict__ w, const float* __restrict__ bias) {
    int b0 = blockIdx.x * 2, t = threadIdx.x;       // 256 threads
    int img = t >> 7, oc = t & 127;
    __shared__ float ins[2][64*49];                 // 25.1 KB
    for (int j = t; j < 2*64*49; j += 256) ins[j/3136][j%3136] = g_h1[b0*3136 + j];
    __syncthreads();
    const float* inp = ins[img];
    float acc[36];
    {
        float bv = bias[oc];
        #pragma unroll
        for (int p = 0; p < 36; p++) acc[p] = bv;
    }
    const float4* wp4 = (const float4*)(w + oc*256);
    for (int ic = 0; ic < 64; ic++) {
        float4 wv = wp4[ic];
        const float* r = &inp[ic*49];
        #pragma unroll
        for (int y = 0; y < 6; y++)
            #pragma unroll
            for (int xx = 0; xx < 6; xx++)
                acc[y*6+xx] += wv.x*r[y*7+xx] + wv.y*r[y*7+xx+1]
                             + wv.z*r[y*7+xx+7] + wv.w*r[y*7+xx+8];
    }
    float* outp = &g_h2[(b0+img)*4608 + oc*36];
    #pragma unroll
    for (int p = 0; p < 36; p++) outp[p] = gelu_exact(acc[p]);
}

// conv3: [B,128,6,6] -> [B,256,5,5]. One out-channel per thread, 1 image/block.
__global__ void conv3_kernel(const float* __restrict__ w, const float* __restrict__ bias) {
    int b = blockIdx.x, oc = threadIdx.x;           // 256 threads
    __shared__ float ins[128*36];                   // 18 KB
    for (int j = oc; j < 128*36; j += 256) ins[j] = g_h2[b*4608 + j];
    __syncthreads();
    float acc[25];
    {
        float bv = bias[oc];
        #pragma unroll
        for (int p = 0; p < 25; p++) acc[p] = bv;
    }
    const float4* wp4 = (const float4*)(w + oc*512);
    for (int ic = 0; ic < 128; ic++) {
        float4 wv = wp4[ic];
        const float* r = &ins[ic*36];
        #pragma unroll
        for (int y = 0; y < 5; y++)
            #pragma unroll
            for (int xx = 0; xx < 5; xx++)
                acc[y*5+xx] += wv.x*r[y*6+xx] + wv.y*r[y*6+xx+1]
                             + wv.z*r[y*6+xx+6] + wv.w*r[y*6+xx+7];
    }
    float* outp = &g_h3[b*6400 + oc*25];
    #pragma unroll
    for (int p = 0; p < 25; p++) outp[p] = gelu_exact(acc[p]);
}

// primary caps: [B,256,5,5] -> [B,96,16] + squash. One caps-channel per thread, 1 img/block.
__global__ void pc_kernel(const float* __restrict__ w, const float* __restrict__ bias) {
    int b = blockIdx.x, oc = threadIdx.x;           // 96 threads
    __shared__ float ins[256*25];                   // 25.6 KB
    for (int j = oc; j < 256*25; j += 96) ins[j] = g_h3[b*6400 + j];
    __syncthreads();
    float acc[16];
    {
        float bv = bias[oc];
        #pragma unroll
        for (int p = 0; p < 16; p++) acc[p] = bv;
    }
    const float4* wp4 = (const float4*)(w + oc*1024);
    for (int ic = 0; ic < 256; ic++) {
        float4 wv = wp4[ic];
        const float* r = &ins[ic*25];
        #pragma unroll
        for (int y = 0; y < 4; y++)
            #pragma unroll
            for (int xx = 0; xx < 4; xx++)
                acc[y*4+xx] += wv.x*r[y*5+xx] + wv.y*r[y*5+xx+1]
                             + wv.z*r[y*5+xx+5] + wv.w*r[y*5+xx+6];
    }
    float n2 = 0.f;
    #pragma unroll
    for (int d = 0; d < 16; d++) n2 += acc[d]*acc[d];
    float n = sqrtf(n2);
    float sc = (1.0f - expf(-n)) / (n + 1e-8f);
    float* outp = &g_u[(b*96 + oc)*16];
    #pragma unroll
    for (int d = 0; d < 16; d++) outp[d] = acc[d] * sc;
}

// ---------------- capsule layer ---------------------------------------------
// c1[o,i] = softmax over o of caps_b (batch-independent)
__global__ void c1_kernel(const float* __restrict__ caps_b) {
    int i = threadIdx.x;   // 96 threads, 1 block
    float m = -INFINITY;
    for (int o = 0; o < NCAPS; o++) m = fmaxf(m, caps_b[o*ICAPS + i]);
    float s = 0.f;
    for (int o = 0; o < NCAPS; o++) s += expf(caps_b[o*ICAPS + i] - m);
    for (int o = 0; o < NCAPS; o++)
        g_c1[o*ICAPS + i] = expf(caps_b[o*ICAPS + i] - m) / s;
}

// u_hat[o,b,i,d] = sum_k W[o,i,d,k] * u[b,i,k]   (o-major layout for TLB-local writes)
__global__ void einsum_kernel(const float* __restrict__ W) {
    int i = blockIdx.x, o = blockIdx.y;
    __shared__ float Wt[256];    // transposed: Wt[k*16+d] = W[d*16+k]
    __shared__ float usm[64*17];
    int t = threadIdx.x;
    float wv = W[(o*96 + i)*256 + t];   // t = d*16 + k
    Wt[(t & 15)*16 + (t >> 4)] = wv;
    __syncthreads();
    int dq = t & 3, bb = t >> 2;
    float4 wreg[16];   // wreg[k] = {W[dq*4+0..3, k]}
    #pragma unroll
    for (int k = 0; k < 16; k++) wreg[k] = *(const float4*)&Wt[k*16 + dq*4];
    for (int b0 = 0; b0 < BATCH; b0 += 64) {
        __syncthreads();
        #pragma unroll
        for (int r = 0; r < 4; r++) {
            int idx = t + r*256;
            int bb2 = idx >> 4, k2 = idx & 15;
            usm[bb2*17 + k2] = g_u[((b0+bb2)*96 + i)*16 + k2];
        }
        __syncthreads();
        float4 acc = make_float4(0.f, 0.f, 0.f, 0.f);
        #pragma unroll
        for (int k = 0; k < 16; k++) {
            float uv = usm[bb*17 + k];
            acc.x += wreg[k].x * uv; acc.y += wreg[k].y * uv;
            acc.z += wreg[k].z * uv; acc.w += wreg[k].w * uv;
        }
        size_t off = (((size_t)o*BATCH + (b0+bb))*ICAPS + i)*CDIM + dq*4;
        *(float4*)&g_uhat[off] = acc;
    }
}

// per (b,i): online max + sumexp over the 181 out-caps (softmax axis=1)
__global__ void stats_kernel() {
    int b = blockIdx.x, i = threadIdx.x;  // 96 threads
    float m = -INFINITY, s = 0.f;
    for (int o = 0; o < NCAPS; o++) {
        float v = g_blog[(b*NCAPS + o)*ICAPS + i];
        if (v > m) { s = s * expf(m - v) + 1.f; m = v; }
        else       { s += expf(v - m); }
    }
    g_maxl[b*96 + i] = m;
    g_sume[b*96 + i] = s;
}

// one routing step for one (b,o): c -> weighted sum -> squash -> (b update | emit v,len)
// mode 0: iter1 — c from g_c1, logits based on caps_b (no init_blog / stats needed)
// mode 1: iter2 — c from softmax(blog) via stats, update blog
// mode 2: iter3 — c from softmax(blog) via stats, emit x & len
__global__ void route_kernel(const float* __restrict__ caps_b, int mode) {
    int o = blockIdx.x, b = blockIdx.y, t = threadIdx.x;  // 128 threads
    __shared__ float csm[96];
    __shared__ float oldl[96];
    __shared__ float uhsm[96*17];
    __shared__ float red[128];
    __shared__ float ssm[16];
    __shared__ float sc_sm, n_sm;
    if (t < 96) {
        float cval, lv;
        if (mode == 0) {
            cval = g_c1[o*ICAPS + t];
            lv = caps_b[o*ICAPS + t];
        } else {
            lv = g_blog[(b*NCAPS + o)*ICAPS + t];
            cval = expf(lv - g_maxl[b*96 + t]) / g_sume[b*96 + t];
        }
        csm[t] = cval;
        oldl[t] = lv;
        const float4* uh = (const float4*)&g_uhat[(((size_t)o*BATCH + b)*ICAPS + t)*CDIM];
        float4 q0 = uh[0], q1 = uh[1], q2 = uh[2], q3 = uh[3];
        float* dst = &uhsm[t*17];
        dst[0]=q0.x; dst[1]=q0.y; dst[2]=q0.z; dst[3]=q0.w;
        dst[4]=q1.x; dst[5]=q1.y; dst[6]=q1.z; dst[7]=q1.w;
        dst[8]=q2.x; dst[9]=q2.y; dst[10]=q2.z; dst[11]=q2.w;
        dst[12]=q3.x; dst[13]=q3.y; dst[14]=q3.z; dst[15]=q3.w;
    }
    __syncthreads();
    int k = t & 15, part = t >> 4;  // 8 partials per k
    float partial = 0.f;
    for (int i = part; i < 96; i += 8) partial += csm[i] * uhsm[i*17 + k];
    red[part*16 + k] = partial;
    __syncthreads();
    if (t < 16) {
        float s = 0.f;
        #pragma unroll
        for (int p = 0; p < 8; p++) s += red[p*16 + t];
        ssm[t] = s;
    }
    __syncthreads();
    if (t == 0) {
        float n2 = 0.f;
        #pragma unroll
        for (int kk = 0; kk < 16; kk++) n2 += ssm[kk]*ssm[kk];
        float n = sqrtf(n2);
        sc_sm = (1.0f - expf(-n)) / (n + 1e-8f);
        n_sm = n;
    }
    __syncthreads();
    if (mode != 2) {
        if (t < 96) {
            float dot = 0.f;
            #pragma unroll
            for (int kk = 0; kk < 16; kk++) dot += ssm[kk] * uhsm[t*17 + kk];
            g_blog[(b*NCAPS + o)*ICAPS + t] = oldl[t] + sc_sm * dot;
        }
    } else {
        if (t < 16) g_x[(b*NCAPS + o)*CDIM + t] = ssm[t] * sc_sm;
        if (t == 0) g_len[b*NCAPS + o] = n_sm * sc_sm;
    }
}

// ---------------- peak picking ----------------------------------------------
__global__ void peak_kernel(float* __restrict__ out_len) {
    int b = blockIdx.x, t = threadIdx.x;  // 256 threads
    __shared__ float nl[NCAPS];
    __shared__ float pk[NCAPS];
    __shared__ float ssum;
    if (t < NCAPS) nl[t] = g_len[b*NCAPS + t];
    __syncthreads();
    if (t == 0) {
        float s = 0.f;
        for (int o = 0; o < NCAPS; o++) s += nl[o];
        ssum = s + 1e-8f;
    }
    __syncthreads();
    if (t < NCAPS) {
        float v = nl[t] / ssum;
        nl[t] = v;
        out_len[b*NCAPS + t] = v;
    }
    __syncthreads();
    if (t < NCAPS) {
        int lo = t - 5; if (lo < 0) lo = 0;
        int hi = t + 5; if (hi > NCAPS-1) hi = NCAPS-1;
        float m = -INFINITY;
        for (int j = lo; j <= hi; j++) m = fmaxf(m, nl[j]);
        pk[t] = (nl[t] == m) ? nl[t] : 0.f;
    }
    __syncthreads();
    if (t == 0) {
        int chosen[TOPK];
        for (int kk = 0; kk < TOPK; kk++) {
            float best = -INFINITY; int bi = 0;
            for (int j = 0; j < NCAPS; j++)
                if (pk[j] > best) { best = pk[j]; bi = j; }
            chosen[kk] = bi;
            pk[bi] = -INFINITY;
        }
        for (int a = 0; a < TOPK-1; a++)
            for (int c = 0; c < TOPK-1-a; c++)
                if (chosen[c] > chosen[c+1]) { int tmp = chosen[c]; chosen[c] = chosen[c+1]; chosen[c+1] = tmp; }
        for (int kk = 0; kk < TOPK; kk++) g_idx[b*TOPK + kk] = chosen[kk];
    }
}

// ---------------- MLP --------------------------------------------------------
// fc1 exploits one-hot sparsity: only rows [idx*16, idx*16+16) of fc1_w matter.
__global__ void fc1_kernel(const float* __restrict__ w, const float* __restrict__ bias) {
    int r = blockIdx.x, t = threadIdx.x;  // 256 threads, r in [0,2048)
    int b = r >> 2;
    int idx = g_idx[r];
    __shared__ float xf[16];
    if (t < 16) xf[t] = g_x[(b*NCAPS + idx)*CDIM + t];
    __syncthreads();
    for (int j = t; j < 1024; j += 256) {
        float acc = bias[j];
        #pragma unroll
        for (int d = 0; d < 16; d++) acc += xf[d] * w[(idx*16 + d)*1024 + j];
        g_f1[r*1024 + j] = gelu_exact(acc);
    }
}

// 128x64 tiled SGEMM: C = act(A[M,K] @ B[K,N] + bias). M%128==0, N%64==0, K%16==0.
// trans_head: scatter-store as W_out[b, a, kk] instead of row-major C.
__global__ void sgemm_kernel(const float* __restrict__ A, const float* __restrict__ Bw,
                             const float* __restrict__ bias, float* __restrict__ C,
                             int M, int N, int K, int apply_gelu, int trans_head) {
    __shared__ float As[16][132];
    __shared__ float Bs[16][68];
    int tid = threadIdx.x;                  // 256 threads
    int tm = tid >> 4, tn = tid & 15;
    int rowBase = blockIdx.y * 128;
    int colBase = blockIdx.x * 64;
    float acc[8][4];
    {
        float bv[4];
        #pragma unroll
        for (int j = 0; j < 4; j++) bv[j] = bias[colBase + tn*4 + j];
        #pragma unroll
        for (int i = 0; i < 8; i++)
            #pragma unroll
            for (int j = 0; j < 4; j++) acc[i][j] = bv[j];
    }
    int arow = tid >> 1, ak = (tid & 1) * 8;
    int brow = tid >> 4, bcol = (tid & 15) * 4;
    for (int k0 = 0; k0 < K; k0 += 16) {
        const float* ap = &A[(size_t)(rowBase + arow)*K + k0 + ak];
        float4 a0 = *(const float4*)ap;
        float4 a1 = *(const float4*)(ap + 4);
        As[ak+0][arow] = a0.x; As[ak+1][arow] = a0.y; As[ak+2][arow] = a0.z; As[ak+3][arow] = a0.w;
        As[ak+4][arow] = a1.x; As[ak+5][arow] = a1.y; As[ak+6][arow] = a1.z; As[ak+7][arow] = a1.w;
        float4 bv = *(const float4*)&Bw[(size_t)(k0 + brow)*N + colBase + bcol];
        *(float4*)&Bs[brow][bcol] = bv;
        __syncthreads();
        #pragma unroll
        for (int kk = 0; kk < 16; kk++) {
            float4 b4 = *(const float4*)&Bs[kk][tn*4];
            float4 a4 = *(const float4*)&As[kk][tm*8];
            float4 a5 = *(const float4*)&As[kk][tm*8+4];
            acc[0][0] += a4.x*b4.x; acc[0][1] += a4.x*b4.y; acc[0][2] += a4.x*b4.z; acc[0][3] += a4.x*b4.w;
            acc[1][0] += a4.y*b4.x; acc[1][1] += a4.y*b4.y; acc[1][2] += a4.y*b4.z; acc[1][3] += a4.y*b4.w;
            acc[2][0] += a4.z*b4.x; acc[2][1] += a4.z*b4.y; acc[2][2] += a4.z*b4.z; acc[2][3] += a4.z*b4.w;
            acc[3][0] += a4.w*b4.x; acc[3][1] += a4.w*b4.y; acc[3][2] += a4.w*b4.z; acc[3][3] += a4.w*b4.w;
            acc[4][0] += a5.x*b4.x; acc[4][1] += a5.x*b4.y; acc[4][2] += a5.x*b4.z; acc[4][3] += a5.x*b4.w;
            acc[5][0] += a5.y*b4.x; acc[5][1] += a5.y*b4.y; acc[5][2] += a5.y*b4.z; acc[5][3] += a5.y*b4.w;
            acc[6][0] += a5.z*b4.x; acc[6][1] += a5.z*b4.y; acc[6][2] += a5.z*b4.z; acc[6][3] += a5.z*b4.w;
            acc[7][0] += a5.w*b4.x; acc[7][1] += a5.w*b4.y; acc[7][2] += a5.w*b4.z; acc[7][3] += a5.w*b4.w;
        }
        __syncthreads();
    }
    #pragma unroll
    for (int i = 0; i < 8; i++) {
        int r = rowBase + tm*8 + i;
        #pragma unroll
        for (int j = 0; j < 4; j++) {
            int n = colBase + tn*4 + j;
            float v = acc[i][j];
            if (apply_gelu) v = gelu_exact(v);
            if (!trans_head) C[(size_t)r*N + n] = v;
            else {
                int b = r >> 2, kk = r & 3;
                C[(b*A2 + n)*TOPK + kk] = v;   // W_out[b, a, k]
            }
        }
    }
}

// ---------------- launcher ---------------------------------------------------
extern "C" void kernel_launch(void* const* d_in, const int* in_sizes, int n_in,
                              void* d_out, int out_size) {
    const float* scm     = (const float*)d_in[0];
    const float* conv1_w = (const float*)d_in[2];
    const float* conv1_b = (const float*)d_in[3];
    const float* conv2_w = (const float*)d_in[4];
    const float* conv2_b = (const float*)d_in[5];
    const float* conv3_w = (const float*)d_in[6];
    const float* conv3_b = (const float*)d_in[7];
    const float* pc_w    = (const float*)d_in[8];
    const float* pc_b    = (const float*)d_in[9];
    const float* caps_W  = (const float*)d_in[10];
    const float* caps_b  = (const float*)d_in[11];
    const float* fc1_w   = (const float*)d_in[12];
    const float* fc1_b   = (const float*)d_in[13];
    const float* fc2_w   = (const float*)d_in[14];
    const float* fc2_b   = (const float*)d_in[15];
    const float* fc3_w   = (const float*)d_in[16];
    const float* fc3_b   = (const float*)d_in[17];
    const float* fc4_w   = (const float*)d_in[18];
    const float* fc4_b   = (const float*)d_in[19];
    const float* fc5_w   = (const float*)d_in[20];
    const float* fc5_b   = (const float*)d_in[21];
    const float* head_w  = (const float*)d_in[22];
    const float* head_b  = (const float*)d_in[23];
    float* out = (float*)d_out;

    // conv stack
    conv1_kernel<<<BATCH, 256>>>(scm, conv1_w, conv1_b);
    conv2_kernel<<<BATCH/2, 256>>>(conv2_w, conv2_b);
    conv3_kernel<<<BATCH, 256>>>(conv3_w, conv3_b);
    pc_kernel<<<BATCH, 96>>>(pc_w, pc_b);

    // capsule layer: c1 precompute kills init_blog + stats1
    c1_kernel<<<1, 96>>>(caps_b);
    einsum_kernel<<<dim3(ICAPS, NCAPS), 256>>>(caps_W);
    route_kernel<<<dim3(NCAPS, BATCH), 128>>>(caps_b, 0);   // iter1 (c1, base=caps_b)
    stats_kernel<<<BATCH, 96>>>();
    route_kernel<<<dim3(NCAPS, BATCH), 128>>>(caps_b, 1);   // iter2
    stats_kernel<<<BATCH, 96>>>();
    route_kernel<<<dim3(NCAPS, BATCH), 128>>>(caps_b, 2);   // iter3 (emit)

    // peaks + length output (length lives after W_out in d_out)
    float* out_len = out + BATCH * A2 * TOPK;
    peak_kernel<<<BATCH, 256>>>(out_len);

    // MLP
    float* g_f1p; cudaGetSymbolAddress((void**)&g_f1p, g_f1);
    float* g_f2p; cudaGetSymbolAddress((void**)&g_f2p, g_f2);
    float* g_f3p; cudaGetSymbolAddress((void**)&g_f3p, g_f3);
    float* g_f4p; cudaGetSymbolAddress((void**)&g_f4p, g_f4);
    float* g_f5p; cudaGetSymbolAddress((void**)&g_f5p, g_f5);

    fc1_kernel<<<MLPM, 256>>>(fc1_w, fc1_b);
    sgemm_kernel<<<dim3(768/64, MLPM/128), 256>>>(g_f1p, fc2_w, fc2_b, g_f2p, MLPM, 768, 1024, 1, 0);
    sgemm_kernel<<<dim3(512/64, MLPM/128), 256>>>(g_f2p, fc3_w, fc3_b, g_f3p, MLPM, 512,  768, 1, 0);
    sgemm_kernel<<<dim3(512/64, MLPM/128), 256>>>(g_f3p, fc4_w, fc4_b, g_f4p, MLPM, 512,  512, 1, 0);
    sgemm_kernel<<<dim3(256/64, MLPM/128), 256>>>(g_f4p, fc5_w, fc5_b, g_f5p, MLPM, 256,  512, 1, 0);
    sgemm_kernel<<<dim3(128/64, MLPM/128), 256>>>(g_f5p, head_w, head_b, out,  MLPM, 128,  256, 0, 1);
    (void)in_sizes; (void)n_in; (void)out_size;
}